// round 5
// baseline (speedup 1.0000x reference)
#include <cuda_runtime.h>
#include <cstdint>

// Problem constants
#define B_   1024
#define N_   256
#define C_   128
#define H_   4
#define DH   32
#define T_   4
#define INTV 64
#define KN   192   // keys per slice = N - INTV

// Scratch (device globals; no dynamic allocation allowed)
__device__ float g_q[(size_t)B_*H_*N_*DH];       // [b][h][n][d]
__device__ float g_k[(size_t)B_*H_*N_*DH];
__device__ float g_v[(size_t)B_*H_*N_*DH];
__device__ float g_bias[T_*H_*INTV*KN];          // [i][h][q][kk]

// ---------------------------------------------------------------------------
// helpers
// ---------------------------------------------------------------------------
__device__ __forceinline__ uint32_t f2tf(float f) {
    uint32_t u;
    asm("cvt.rna.tf32.f32 %0, %1;" : "=r"(u) : "f"(f));
    return u;
}

__device__ __forceinline__ void mma_tf32(float4& d,
                                         uint32_t a0, uint32_t a1, uint32_t a2, uint32_t a3,
                                         uint32_t b0, uint32_t b1) {
    asm volatile(
        "mma.sync.aligned.m16n8k8.row.col.f32.tf32.tf32.f32 "
        "{%0,%1,%2,%3}, {%4,%5,%6,%7}, {%8,%9}, {%0,%1,%2,%3};"
        : "+f"(d.x), "+f"(d.y), "+f"(d.z), "+f"(d.w)
        : "r"(a0), "r"(a1), "r"(a2), "r"(a3), "r"(b0), "r"(b1));
}

// ---------------------------------------------------------------------------
// Bias precompute
// ---------------------------------------------------------------------------
__global__ void bias_kernel(const float* __restrict__ rpb,
                            const int* __restrict__ rel) {
    int idx = blockIdx.x * 256 + threadIdx.x;
    if (idx >= T_*H_*INTV*KN) return;
    int kk = idx % KN;
    int q  = (idx / KN) % INTV;
    int h  = (idx / (KN*INTV)) % H_;
    int i  =  idx / (KN*INTV*H_);
    int qg = i*INTV + q;
    int kg = (kk < i*INTV) ? kk : kk + INTV;
    g_bias[idx] = rpb[rel[qg*N_ + kg]*H_ + h];
}

// ---------------------------------------------------------------------------
// QKV GEMM: block = 128 M-rows (102 KB smem -> 2 blocks/SM, 32 warps/SM),
// A resident, 6 N-chunks of 64 single-buffered. 16 warps 4(m)x4(n), warp
// tile 32 x 16.
// ---------------------------------------------------------------------------
#define QA_LD 132
#define QB_LD 68

__device__ __forceinline__ void store_qkv(int m, int cg, float2 v) {
    int b = m >> 8, n = m & 255;
    if (cg < 128) {
        int h = cg >> 5, d = cg & 31;
        *(float2*)&g_q[(((size_t)b*H_ + h)*N_ + n)*DH + d] = v;
    } else if (cg < 256) {
        int cc = cg - 128; int h = cc >> 5, d = cc & 31;
        *(float2*)&g_k[(((size_t)b*H_ + h)*N_ + n)*DH + d] = v;
    } else {
        int cc = cg - 256; int h = cc >> 5, d = cc & 31;
        *(float2*)&g_v[(((size_t)b*H_ + h)*N_ + n)*DH + d] = v;
    }
}

__global__ __launch_bounds__(512, 2) void qkv_gemm_tc(const float* __restrict__ x,
                                                      const float* __restrict__ q_w,
                                                      const float* __restrict__ kv_w) {
    extern __shared__ uint32_t sm[];
    uint32_t* As = sm;                   // [128][QA_LD]
    uint32_t* Bs = sm + 128*QA_LD;       // [128][QB_LD]

    int tid   = threadIdx.x;
    int mBase = blockIdx.x * 128;

#pragma unroll
    for (int it = 0; it < 8; ++it) {     // A: 128x128
        int idx = tid + it*512;
        int r = idx >> 5, c4 = idx & 31;
        float4 v = *(const float4*)(x + (size_t)(mBase + r)*128 + c4*4);
        uint32_t* p = As + r*QA_LD + c4*4;
        p[0] = f2tf(v.x); p[1] = f2tf(v.y); p[2] = f2tf(v.z); p[3] = f2tf(v.w);
    }

    int warp = tid >> 5, lane = tid & 31;
    int g = lane >> 2, q = lane & 3;
    int wm = (warp & 3) * 32;
    int wn = (warp >> 2) * 16;

#pragma unroll 1
    for (int c = 0; c < 6; ++c) {
        const float* Bp; int bld, bcol;
        if (c < 2) { Bp = q_w;  bld = 128; bcol = c*64; }
        else       { Bp = kv_w; bld = 256; bcol = (c-2)*64; }

        __syncthreads();
#pragma unroll
        for (int it = 0; it < 4; ++it) {  // B chunk: 128x64
            int idx = tid + it*512;
            int r = idx >> 4, c4 = idx & 15;
            float4 v = *(const float4*)(Bp + (size_t)r*bld + bcol + c4*4);
            uint32_t* p = Bs + r*QB_LD + c4*4;
            p[0] = f2tf(v.x); p[1] = f2tf(v.y); p[2] = f2tf(v.z); p[3] = f2tf(v.w);
        }
        __syncthreads();

        float4 acc[2][2];
#pragma unroll
        for (int mi = 0; mi < 2; ++mi)
#pragma unroll
            for (int nj = 0; nj < 2; ++nj) acc[mi][nj] = make_float4(0.f,0.f,0.f,0.f);

#pragma unroll
        for (int k0 = 0; k0 < 128; k0 += 8) {
            uint32_t a[2][4];
#pragma unroll
            for (int mi = 0; mi < 2; ++mi) {
                int r = wm + mi*16 + g;
                a[mi][0] = As[r*QA_LD + k0 + q];
                a[mi][1] = As[(r+8)*QA_LD + k0 + q];
                a[mi][2] = As[r*QA_LD + k0 + q + 4];
                a[mi][3] = As[(r+8)*QA_LD + k0 + q + 4];
            }
#pragma unroll
            for (int nj = 0; nj < 2; ++nj) {
                uint32_t b0 = Bs[(k0+q)*QB_LD   + wn + nj*8 + g];
                uint32_t b1 = Bs[(k0+q+4)*QB_LD + wn + nj*8 + g];
#pragma unroll
                for (int mi = 0; mi < 2; ++mi)
                    mma_tf32(acc[mi][nj], a[mi][0], a[mi][1], a[mi][2], a[mi][3], b0, b1);
            }
        }

#pragma unroll
        for (int mi = 0; mi < 2; ++mi)
#pragma unroll
            for (int nj = 0; nj < 2; ++nj) {
                int r  = mBase + wm + mi*16 + g;
                int cg = c*64 + wn + nj*8 + 2*q;
                store_qkv(r,     cg, make_float2(acc[mi][nj].x, acc[mi][nj].y));
                store_qkv(r + 8, cg, make_float2(acc[mi][nj].z, acc[mi][nj].w));
            }
    }
}

// ---------------------------------------------------------------------------
// Fused attention + projection: block per window b (1024 blocks, 512 thr).
// Loop h=0..3: K/V head tile staged to smem; Q A-frags loaded straight from
// gmem; per-warp (slice i = w/4, rowsub j = w%4) online-softmax attention
// over 2x96 keys; output written as tf32 into resident att[256][132] smem.
// Then proj_w staged into the freed K/V region and out = att @ proj_w + pb
// computed entirely from smem.
// ---------------------------------------------------------------------------
#define TS_LD 36
#define AT_LD 132

#define ATT_OFF 0
#define KS_OFF  (256*AT_LD)            // 33792
#define VS_OFF  (KS_OFF + 256*TS_LD)   // 43008
#define FUSE_SMEM_WORDS (VS_OFF + 256*TS_LD)  // 52224 (208,896 B)

__global__ __launch_bounds__(512) void attn_proj_tc(const float* __restrict__ pw,
                                                    const float* __restrict__ pb,
                                                    float* __restrict__ out) {
    extern __shared__ uint32_t sm[];
    uint32_t* att = sm + ATT_OFF;      // [256][AT_LD]
    uint32_t* Ks  = sm + KS_OFF;       // [256][TS_LD]
    uint32_t* Vs  = sm + VS_OFF;       // [256][TS_LD]
    uint32_t* PW  = sm + KS_OFF;       // reuse K/V region: [128][AT_LD] = 16896 <= 18432

    int tid = threadIdx.x;
    int b   = blockIdx.x;

    int warp = tid >> 5, lane = tid & 31;
    int g = lane >> 2, q = lane & 3;
    int rbase = warp * 16;             // query rows rbase..rbase+15
    int i = warp >> 2;                 // slice
    int r0 = rbase + g, r1 = r0 + 8;
    int srcA = (lane & ~3) | (q >> 1);
    int srcB = srcA + 2;

    const float scale = 0.17677669529663687f;  // 32^-0.5

    for (int h = 0; h < H_; ++h) {
        size_t base = ((size_t)b*H_ + h) * N_ * DH;
        __syncthreads();   // previous head's mma reads of Ks/Vs complete

#pragma unroll
        for (int it = 0; it < 4; ++it) {   // K,V: 256x32 each
            int idx = tid + it*512;
            int r = idx >> 3, c4 = idx & 7;
            float4 kv = *(const float4*)(g_k + base + (size_t)r*DH + c4*4);
            float4 vv = *(const float4*)(g_v + base + (size_t)r*DH + c4*4);
            uint32_t* pk = Ks + r*TS_LD + c4*4;
            pk[0] = f2tf(kv.x); pk[1] = f2tf(kv.y); pk[2] = f2tf(kv.z); pk[3] = f2tf(kv.w);
            uint32_t* pv = Vs + r*TS_LD + c4*4;
            pv[0] = f2tf(vv.x); pv[1] = f2tf(vv.y); pv[2] = f2tf(vv.z); pv[3] = f2tf(vv.w);
        }

        // Q A-frags direct from gmem (overlaps with staging latency)
        uint32_t qa[4][4];
        {
            const float* qp0 = g_q + base + (size_t)r0*DH;
            const float* qp1 = g_q + base + (size_t)r1*DH;
#pragma unroll
            for (int kc = 0; kc < 4; ++kc) {
                qa[kc][0] = f2tf(qp0[kc*8 + q]     * scale);
                qa[kc][1] = f2tf(qp1[kc*8 + q]     * scale);
                qa[kc][2] = f2tf(qp0[kc*8 + q + 4] * scale);
                qa[kc][3] = f2tf(qp1[kc*8 + q + 4] * scale);
            }
        }
        __syncthreads();

        const float* bb = g_bias + ((size_t)((i*H_ + h)*INTV + (rbase & 63)))*KN;

        float m0r = -1e30f, m1r = -1e30f;
        float s0r = 0.f, s1r = 0.f;
        float4 o[4];
#pragma unroll
        for (int nj = 0; nj < 4; ++nj) o[nj] = make_float4(0.f,0.f,0.f,0.f);

#pragma unroll
        for (int ch = 0; ch < 2; ++ch) {
            int cbase = ch * 96;

            // S frags (16 x 96), bias-initialized
            float4 c[12];
#pragma unroll
            for (int kt = 0; kt < 12; ++kt) {
                int col = cbase + kt*8 + 2*q;
                float2 b0 = *(const float2*)(bb + (size_t)(g)*KN + col);
                float2 b1 = *(const float2*)(bb + (size_t)(g+8)*KN + col);
                c[kt] = make_float4(b0.x, b0.y, b1.x, b1.y);
            }

            // S = scale*Q K^T + bias
#pragma unroll
            for (int kc = 0; kc < 4; ++kc) {
                int k0 = kc*8;
#pragma unroll
                for (int kt = 0; kt < 12; ++kt) {
                    int col = cbase + kt*8;
                    int off = (col >= i*INTV) ? INTV : 0;
                    int kg = col + g + off;
                    uint32_t b0 = Ks[kg*TS_LD + k0 + q];
                    uint32_t b1 = Ks[kg*TS_LD + k0 + q + 4];
                    mma_tf32(c[kt], qa[kc][0], qa[kc][1], qa[kc][2], qa[kc][3], b0, b1);
                }
            }

            // chunk max
            float mx0 = -1e30f, mx1 = -1e30f;
#pragma unroll
            for (int kt = 0; kt < 12; ++kt) {
                mx0 = fmaxf(mx0, fmaxf(c[kt].x, c[kt].y));
                mx1 = fmaxf(mx1, fmaxf(c[kt].z, c[kt].w));
            }
            mx0 = fmaxf(mx0, __shfl_xor_sync(0xffffffffu, mx0, 1));
            mx0 = fmaxf(mx0, __shfl_xor_sync(0xffffffffu, mx0, 2));
            mx1 = fmaxf(mx1, __shfl_xor_sync(0xffffffffu, mx1, 1));
            mx1 = fmaxf(mx1, __shfl_xor_sync(0xffffffffu, mx1, 2));

            float mn0 = fmaxf(m0r, mx0), mn1 = fmaxf(m1r, mx1);
            float sc0 = __expf(m0r - mn0), sc1 = __expf(m1r - mn1);
            m0r = mn0; m1r = mn1;

            // exp + chunk sum
            float cs0 = 0.f, cs1 = 0.f;
#pragma unroll
            for (int kt = 0; kt < 12; ++kt) {
                c[kt].x = __expf(c[kt].x - mn0);
                c[kt].y = __expf(c[kt].y - mn0);
                c[kt].z = __expf(c[kt].z - mn1);
                c[kt].w = __expf(c[kt].w - mn1);
                cs0 += c[kt].x + c[kt].y;
                cs1 += c[kt].z + c[kt].w;
            }
            cs0 += __shfl_xor_sync(0xffffffffu, cs0, 1);
            cs0 += __shfl_xor_sync(0xffffffffu, cs0, 2);
            cs1 += __shfl_xor_sync(0xffffffffu, cs1, 1);
            cs1 += __shfl_xor_sync(0xffffffffu, cs1, 2);
            s0r = s0r*sc0 + cs0;
            s1r = s1r*sc1 + cs1;

            // rescale O
#pragma unroll
            for (int nj = 0; nj < 4; ++nj) {
                o[nj].x *= sc0; o[nj].y *= sc0;
                o[nj].z *= sc1; o[nj].w *= sc1;
            }

            // PV over this chunk's 96 keys
#pragma unroll
            for (int kt = 0; kt < 12; ++kt) {
                float t0 = __shfl_sync(0xffffffffu, c[kt].x, srcA);
                float t1 = __shfl_sync(0xffffffffu, c[kt].y, srcA);
                float t2 = __shfl_sync(0xffffffffu, c[kt].z, srcA);
                float t3 = __shfl_sync(0xffffffffu, c[kt].w, srcA);
                float t4 = __shfl_sync(0xffffffffu, c[kt].x, srcB);
                float t5 = __shfl_sync(0xffffffffu, c[kt].y, srcB);
                float t6 = __shfl_sync(0xffffffffu, c[kt].z, srcB);
                float t7 = __shfl_sync(0xffffffffu, c[kt].w, srcB);
                uint32_t a0 = f2tf((q & 1) ? t1 : t0);
                uint32_t a1 = f2tf((q & 1) ? t3 : t2);
                uint32_t a2 = f2tf((q & 1) ? t5 : t4);
                uint32_t a3 = f2tf((q & 1) ? t7 : t6);
                int col = cbase + kt*8;
                int off = (col >= i*INTV) ? INTV : 0;
                int kg0 = col + q + off;
#pragma unroll
                for (int nj = 0; nj < 4; ++nj) {
                    uint32_t b0 = Vs[kg0*TS_LD     + nj*8 + g];
                    uint32_t b1 = Vs[(kg0+4)*TS_LD + nj*8 + g];
                    mma_tf32(o[nj], a0, a1, a2, a3, b0, b1);
                }
            }
        }

        float inv0 = 1.f / s0r;
        float inv1 = 1.f / s1r;

        // normalize, convert to tf32, write to resident att tile
#pragma unroll
        for (int nj = 0; nj < 4; ++nj) {
            int cb = h*DH + nj*8 + 2*q;
            att[r0*AT_LD + cb]     = f2tf(o[nj].x * inv0);
            att[r0*AT_LD + cb + 1] = f2tf(o[nj].y * inv0);
            att[r1*AT_LD + cb]     = f2tf(o[nj].z * inv1);
            att[r1*AT_LD + cb + 1] = f2tf(o[nj].w * inv1);
        }
    }

    // ---- projection phase: out = att @ proj_w + pb (all from smem) ----
    __syncthreads();
#pragma unroll
    for (int it = 0; it < 8; ++it) {   // proj_w: 128x128 into PW (K/V region)
        int idx = tid + it*512;
        int r = idx >> 5, c4 = idx & 31;
        float4 v = *(const float4*)(pw + (size_t)r*128 + c4*4);
        uint32_t* p = PW + r*AT_LD + c4*4;
        p[0] = f2tf(v.x); p[1] = f2tf(v.y); p[2] = f2tf(v.z); p[3] = f2tf(v.w);
    }
    __syncthreads();

    int wm = (warp & 3) * 64;
    int wn = (warp >> 2) * 32;

    float4 acc[4][4];
#pragma unroll
    for (int mi = 0; mi < 4; ++mi)
#pragma unroll
        for (int nj = 0; nj < 4; ++nj) acc[mi][nj] = make_float4(0.f,0.f,0.f,0.f);

#pragma unroll
    for (int k0 = 0; k0 < 128; k0 += 8) {
        uint32_t a[4][4];
#pragma unroll
        for (int mi = 0; mi < 4; ++mi) {
            int r = wm + mi*16 + g;
            a[mi][0] = att[r*AT_LD + k0 + q];
            a[mi][1] = att[(r+8)*AT_LD + k0 + q];
            a[mi][2] = att[r*AT_LD + k0 + q + 4];
            a[mi][3] = att[(r+8)*AT_LD + k0 + q + 4];
        }
#pragma unroll
        for (int nj = 0; nj < 4; ++nj) {
            uint32_t b0 = PW[(k0+q)*AT_LD   + wn + nj*8 + g];
            uint32_t b1 = PW[(k0+q+4)*AT_LD + wn + nj*8 + g];
#pragma unroll
            for (int mi = 0; mi < 4; ++mi)
                mma_tf32(acc[mi][nj], a[mi][0], a[mi][1], a[mi][2], a[mi][3], b0, b1);
        }
    }

    int mBase = b * N_;
#pragma unroll
    for (int nj = 0; nj < 4; ++nj) {
        int cg = wn + nj*8 + 2*q;
        float2 bias = *(const float2*)(pb + cg);
#pragma unroll
        for (int mi = 0; mi < 4; ++mi) {
            int r = mBase + wm + mi*16 + g;
            float2 v0 = make_float2(acc[mi][nj].x + bias.x, acc[mi][nj].y + bias.y);
            float2 v1 = make_float2(acc[mi][nj].z + bias.x, acc[mi][nj].w + bias.y);
            *(float2*)&out[(size_t)r*C_ + cg]     = v0;
            *(float2*)&out[(size_t)(r+8)*C_ + cg] = v1;
        }
    }
}

// ---------------------------------------------------------------------------
// Launch
// ---------------------------------------------------------------------------
extern "C" void kernel_launch(void* const* d_in, const int* in_sizes, int n_in,
                              void* d_out, int out_size) {
    const float* x      = (const float*)d_in[0];
    const float* q_w    = (const float*)d_in[1];
    const float* kv_w   = (const float*)d_in[2];
    const float* proj_w = (const float*)d_in[3];
    const float* proj_b = (const float*)d_in[4];
    const float* rpb    = (const float*)d_in[5];
    const int*   rel    = (const int*)d_in[6];
    float* out = (float*)d_out;

    const int qkv_smem  = (128*QA_LD + 128*QB_LD) * 4;   // 102,400 B -> 2 blocks/SM
    const int fuse_smem = FUSE_SMEM_WORDS * 4;           // 208,896 B
    cudaFuncSetAttribute(qkv_gemm_tc,  cudaFuncAttributeMaxDynamicSharedMemorySize, qkv_smem);
    cudaFuncSetAttribute(attn_proj_tc, cudaFuncAttributeMaxDynamicSharedMemorySize, fuse_smem);

    bias_kernel<<<(T_*H_*INTV*KN + 255)/256, 256>>>(rpb, rel);
    qkv_gemm_tc<<<(B_*N_)/128, 512, qkv_smem>>>(x, q_w, kv_w);
    attn_proj_tc<<<B_, 512, fuse_smem>>>(proj_w, proj_b, out);
}

// round 6
// speedup vs baseline: 1.1611x; 1.1611x over previous
#include <cuda_runtime.h>
#include <cstdint>

// Problem constants
#define B_   1024
#define N_   256
#define C_   128
#define H_   4
#define T_   4
#define DH   32
#define INTV 64
#define KN   192   // keys per slice = N - INTV

// Scratch (device globals; no dynamic allocation allowed)
__device__ float g_q[(size_t)B_*H_*N_*DH];       // [b][h][n][d]
__device__ float g_k[(size_t)B_*H_*N_*DH];
__device__ float g_v[(size_t)B_*H_*N_*DH];
__device__ float g_att[(size_t)B_*N_*C_];        // attention output, [b*n][c]
__device__ float g_bias[T_*H_*INTV*KN];          // [i][h][q][kk]

// ---------------------------------------------------------------------------
// helpers
// ---------------------------------------------------------------------------
__device__ __forceinline__ uint32_t f2tf(float f) {
    uint32_t u;
    asm("cvt.rna.tf32.f32 %0, %1;" : "=r"(u) : "f"(f));
    return u;
}

__device__ __forceinline__ void mma_tf32(float4& d,
                                         uint32_t a0, uint32_t a1, uint32_t a2, uint32_t a3,
                                         uint32_t b0, uint32_t b1) {
    asm volatile(
        "mma.sync.aligned.m16n8k8.row.col.f32.tf32.tf32.f32 "
        "{%0,%1,%2,%3}, {%4,%5,%6,%7}, {%8,%9}, {%0,%1,%2,%3};"
        : "+f"(d.x), "+f"(d.y), "+f"(d.z), "+f"(d.w)
        : "r"(a0), "r"(a1), "r"(a2), "r"(a3), "r"(b0), "r"(b1));
}

// ---------------------------------------------------------------------------
// Bias precompute
// ---------------------------------------------------------------------------
__global__ void bias_kernel(const float* __restrict__ rpb,
                            const int* __restrict__ rel) {
    int idx = blockIdx.x * 256 + threadIdx.x;
    if (idx >= T_*H_*INTV*KN) return;
    int kk = idx % KN;
    int q  = (idx / KN) % INTV;
    int h  = (idx / (KN*INTV)) % H_;
    int i  =  idx / (KN*INTV*H_);
    int qg = i*INTV + q;
    int kg = (kk < i*INTV) ? kk : kk + INTV;
    g_bias[idx] = rpb[rel[qg*N_ + kg]*H_ + h];
}

// ---------------------------------------------------------------------------
// QKV GEMM: block = 256 M-rows, A resident (read-once), 6 N-chunks of 64,
// double-buffered B with register prefetch. 512 threads, 16 warps 4(m)x4(n).
// (identical to the verified R4 version)
// ---------------------------------------------------------------------------
#define QA_LD 132
#define QB_LD 68

__device__ __forceinline__ void store_qkv(int m, int cg, float2 v) {
    int b = m >> 8, n = m & 255;
    if (cg < 128) {
        int h = cg >> 5, d = cg & 31;
        *(float2*)&g_q[(((size_t)b*H_ + h)*N_ + n)*DH + d] = v;
    } else if (cg < 256) {
        int cc = cg - 128; int h = cc >> 5, d = cc & 31;
        *(float2*)&g_k[(((size_t)b*H_ + h)*N_ + n)*DH + d] = v;
    } else {
        int cc = cg - 256; int h = cc >> 5, d = cc & 31;
        *(float2*)&g_v[(((size_t)b*H_ + h)*N_ + n)*DH + d] = v;
    }
}

__global__ __launch_bounds__(512) void qkv_gemm_tc(const float* __restrict__ x,
                                                   const float* __restrict__ q_w,
                                                   const float* __restrict__ kv_w) {
    extern __shared__ uint32_t sm[];
    uint32_t* As = sm;                    // [256][QA_LD]
    uint32_t* Bs0 = sm + 256*QA_LD;       // [128][QB_LD] x2 buffers
    uint32_t* Bs1 = Bs0 + 128*QB_LD;

    int tid   = threadIdx.x;
    int mBase = blockIdx.x * 256;

#pragma unroll
    for (int it = 0; it < 16; ++it) {     // A: 256x128
        int idx = tid + it*512;
        int r = idx >> 5, c4 = idx & 31;
        float4 v = *(const float4*)(x + (size_t)(mBase + r)*128 + c4*4);
        uint32_t* p = As + r*QA_LD + c4*4;
        p[0] = f2tf(v.x); p[1] = f2tf(v.y); p[2] = f2tf(v.z); p[3] = f2tf(v.w);
    }
    // B chunk 0 -> Bs0
#pragma unroll
    for (int it = 0; it < 4; ++it) {
        int idx = tid + it*512;
        int rr = idx >> 4, c4 = idx & 15;
        float4 v = *(const float4*)(q_w + (size_t)rr*128 + c4*4);
        uint32_t* p = Bs0 + rr*QB_LD + c4*4;
        p[0] = f2tf(v.x); p[1] = f2tf(v.y); p[2] = f2tf(v.z); p[3] = f2tf(v.w);
    }
    __syncthreads();

    int warp = tid >> 5, lane = tid & 31;
    int g = lane >> 2, q = lane & 3;
    int wm = (warp & 3) * 64;
    int wn = (warp >> 2) * 16;

#pragma unroll
    for (int c = 0; c < 6; ++c) {
        uint32_t* Bcur = (c & 1) ? Bs1 : Bs0;
        uint32_t* Bnxt = (c & 1) ? Bs0 : Bs1;

        // prefetch next chunk to registers (global latency hidden by mma)
        float4 pre[4];
        if (c < 5) {
            int cn = c + 1;
            const float* Bp; int bld, bcol;
            if (cn < 2) { Bp = q_w;  bld = 128; bcol = cn*64; }
            else        { Bp = kv_w; bld = 256; bcol = (cn-2)*64; }
#pragma unroll
            for (int it = 0; it < 4; ++it) {
                int idx = tid + it*512;
                int rr = idx >> 4, c4 = idx & 15;
                pre[it] = *(const float4*)(Bp + (size_t)rr*bld + bcol + c4*4);
            }
        }

        float4 acc[4][2];
#pragma unroll
        for (int mi = 0; mi < 4; ++mi)
#pragma unroll
            for (int nj = 0; nj < 2; ++nj) acc[mi][nj] = make_float4(0.f,0.f,0.f,0.f);

#pragma unroll
        for (int k0 = 0; k0 < 128; k0 += 8) {
            uint32_t a[4][4];
#pragma unroll
            for (int mi = 0; mi < 4; ++mi) {
                int r = wm + mi*16 + g;
                a[mi][0] = As[r*QA_LD + k0 + q];
                a[mi][1] = As[(r+8)*QA_LD + k0 + q];
                a[mi][2] = As[r*QA_LD + k0 + q + 4];
                a[mi][3] = As[(r+8)*QA_LD + k0 + q + 4];
            }
#pragma unroll
            for (int nj = 0; nj < 2; ++nj) {
                uint32_t b0 = Bcur[(k0+q)*QB_LD   + wn + nj*8 + g];
                uint32_t b1 = Bcur[(k0+q+4)*QB_LD + wn + nj*8 + g];
#pragma unroll
                for (int mi = 0; mi < 4; ++mi)
                    mma_tf32(acc[mi][nj], a[mi][0], a[mi][1], a[mi][2], a[mi][3], b0, b1);
            }
        }

        // stage prefetched B into the other buffer
        if (c < 5) {
#pragma unroll
            for (int it = 0; it < 4; ++it) {
                int idx = tid + it*512;
                int rr = idx >> 4, c4 = idx & 15;
                uint32_t* p = Bnxt + rr*QB_LD + c4*4;
                p[0] = f2tf(pre[it].x); p[1] = f2tf(pre[it].y);
                p[2] = f2tf(pre[it].z); p[3] = f2tf(pre[it].w);
            }
        }

#pragma unroll
        for (int mi = 0; mi < 4; ++mi)
#pragma unroll
            for (int nj = 0; nj < 2; ++nj) {
                int r  = mBase + wm + mi*16 + g;
                int cg = c*64 + wn + nj*8 + 2*q;
                store_qkv(r,     cg, make_float2(acc[mi][nj].x, acc[mi][nj].y));
                store_qkv(r + 8, cg, make_float2(acc[mi][nj].z, acc[mi][nj].w));
            }
        __syncthreads();
    }
}

// ---------------------------------------------------------------------------
// Projection GEMM: block = 256 x 128 (single N pass, A read-once).
// (identical to the verified R4 version)
// ---------------------------------------------------------------------------
#define PB_LD 132

__global__ __launch_bounds__(512) void proj_gemm_tc(const float* __restrict__ pw,
                                                    const float* __restrict__ pb,
                                                    float* __restrict__ out) {
    extern __shared__ uint32_t sm[];
    uint32_t* As = sm;                   // [256][QA_LD]
    uint32_t* Bs = sm + 256*QA_LD;       // [128][PB_LD]

    int tid   = threadIdx.x;
    int mBase = blockIdx.x * 256;

#pragma unroll
    for (int it = 0; it < 16; ++it) {
        int idx = tid + it*512;
        int r = idx >> 5, c4 = idx & 31;
        float4 v = *(const float4*)(g_att + (size_t)(mBase + r)*128 + c4*4);
        uint32_t* p = As + r*QA_LD + c4*4;
        p[0] = f2tf(v.x); p[1] = f2tf(v.y); p[2] = f2tf(v.z); p[3] = f2tf(v.w);
    }
#pragma unroll
    for (int it = 0; it < 8; ++it) {
        int idx = tid + it*512;
        int r = idx >> 5, c4 = idx & 31;
        float4 v = *(const float4*)(pw + (size_t)r*128 + c4*4);
        uint32_t* p = Bs + r*PB_LD + c4*4;
        p[0] = f2tf(v.x); p[1] = f2tf(v.y); p[2] = f2tf(v.z); p[3] = f2tf(v.w);
    }
    __syncthreads();

    int warp = tid >> 5, lane = tid & 31;
    int g = lane >> 2, q = lane & 3;
    int wm = (warp & 3) * 64;
    int wn = (warp >> 2) * 32;

    float4 acc[4][4];
#pragma unroll
    for (int mi = 0; mi < 4; ++mi)
#pragma unroll
        for (int nj = 0; nj < 4; ++nj) acc[mi][nj] = make_float4(0.f,0.f,0.f,0.f);

#pragma unroll
    for (int k0 = 0; k0 < 128; k0 += 8) {
        uint32_t a[4][4];
#pragma unroll
        for (int mi = 0; mi < 4; ++mi) {
            int r = wm + mi*16 + g;
            a[mi][0] = As[r*QA_LD + k0 + q];
            a[mi][1] = As[(r+8)*QA_LD + k0 + q];
            a[mi][2] = As[r*QA_LD + k0 + q + 4];
            a[mi][3] = As[(r+8)*QA_LD + k0 + q + 4];
        }
#pragma unroll
        for (int nj = 0; nj < 4; ++nj) {
            uint32_t b0 = Bs[(k0+q)*PB_LD   + wn + nj*8 + g];
            uint32_t b1 = Bs[(k0+q+4)*PB_LD + wn + nj*8 + g];
#pragma unroll
            for (int mi = 0; mi < 4; ++mi)
                mma_tf32(acc[mi][nj], a[mi][0], a[mi][1], a[mi][2], a[mi][3], b0, b1);
        }
    }

#pragma unroll
    for (int nj = 0; nj < 4; ++nj) {
        int cg = wn + nj*8 + 2*q;
        float2 bias = *(const float2*)(pb + cg);
#pragma unroll
        for (int mi = 0; mi < 4; ++mi) {
            int r = mBase + wm + mi*16 + g;
            float2 v0 = make_float2(acc[mi][nj].x + bias.x, acc[mi][nj].y + bias.y);
            float2 v1 = make_float2(acc[mi][nj].z + bias.x, acc[mi][nj].w + bias.y);
            *(float2*)&out[(size_t)r*C_ + cg]     = v0;
            *(float2*)&out[(size_t)(r+8)*C_ + cg] = v1;
        }
    }
}

// ---------------------------------------------------------------------------
// Attention: block per (b, h, half) -> 8192 blocks, 256 threads (8 warps),
// 2 CTAs/SM (regs<=128, smem 73.7KB). Warp w owns 16 query rows of its half
// (slice i = hb*2 + w/4). K/V (256x32) staged to smem; Q A-frags loaded
// straight from gmem. Online softmax over two 96-key chunks; shuffle
// transform feeds PV mma.
// ---------------------------------------------------------------------------
#define TS_LD 36

__global__ __launch_bounds__(256, 2) void attn_tc() {
    extern __shared__ uint32_t sm[];
    uint32_t* Ks = sm;                   // [256][TS_LD]
    uint32_t* Vs = sm + 256*TS_LD;

    int tid = threadIdx.x;
    int bid = blockIdx.x;
    int hb = bid & 1;
    int h  = (bid >> 1) & 3;
    int b  = bid >> 3;
    size_t base = ((size_t)b*H_ + h) * N_ * DH;

    const float scale = 0.17677669529663687f;  // 32^-0.5

#pragma unroll
    for (int it = 0; it < 8; ++it) {     // K,V: 256x32 each
        int idx = tid + it*256;
        int r = idx >> 3, c4 = idx & 7;
        float4 kv = *(const float4*)(g_k + base + (size_t)r*DH + c4*4);
        float4 vv = *(const float4*)(g_v + base + (size_t)r*DH + c4*4);
        uint32_t* pk = Ks + r*TS_LD + c4*4;
        pk[0] = f2tf(kv.x); pk[1] = f2tf(kv.y); pk[2] = f2tf(kv.z); pk[3] = f2tf(kv.w);
        uint32_t* pv = Vs + r*TS_LD + c4*4;
        pv[0] = f2tf(vv.x); pv[1] = f2tf(vv.y); pv[2] = f2tf(vv.z); pv[3] = f2tf(vv.w);
    }

    int warp = tid >> 5, lane = tid & 31;
    int g = lane >> 2, q = lane & 3;
    int rloc = warp * 16;                // 0..112 within half
    int i = hb*2 + (warp >> 2);          // slice
    int r0g = hb*128 + rloc + g;         // global query rows
    int r1g = r0g + 8;

    // Q A-frags direct from gmem (overlaps K/V staging latency)
    uint32_t qa[4][4];
    {
        const float* qp0 = g_q + base + (size_t)r0g*DH;
        const float* qp1 = g_q + base + (size_t)r1g*DH;
#pragma unroll
        for (int kc = 0; kc < 4; ++kc) {
            qa[kc][0] = f2tf(qp0[kc*8 + q]     * scale);
            qa[kc][1] = f2tf(qp1[kc*8 + q]     * scale);
            qa[kc][2] = f2tf(qp0[kc*8 + q + 4] * scale);
            qa[kc][3] = f2tf(qp1[kc*8 + q + 4] * scale);
        }
    }
    __syncthreads();

    const float* bb = g_bias + ((size_t)((i*H_ + h)*INTV + (rloc & 63)))*KN;
    int srcA = (lane & ~3) | (q >> 1);
    int srcB = srcA + 2;

    float m0r = -1e30f, m1r = -1e30f;
    float s0r = 0.f, s1r = 0.f;
    float4 o[4];
#pragma unroll
    for (int nj = 0; nj < 4; ++nj) o[nj] = make_float4(0.f,0.f,0.f,0.f);

#pragma unroll
    for (int ch = 0; ch < 2; ++ch) {
        int cbase = ch * 96;

        // S frags (16 x 96), bias-initialized
        float4 c[12];
#pragma unroll
        for (int kt = 0; kt < 12; ++kt) {
            int col = cbase + kt*8 + 2*q;
            float2 b0 = *(const float2*)(bb + (size_t)(g)*KN + col);
            float2 b1 = *(const float2*)(bb + (size_t)(g+8)*KN + col);
            c[kt] = make_float4(b0.x, b0.y, b1.x, b1.y);
        }

        // S = scale*Q K^T + bias (keys mapped around excluded slice)
#pragma unroll
        for (int kc = 0; kc < 4; ++kc) {
            int k0 = kc*8;
#pragma unroll
            for (int kt = 0; kt < 12; ++kt) {
                int col = cbase + kt*8;
                int off = (col >= i*INTV) ? INTV : 0;
                int kg = col + g + off;
                uint32_t b0 = Ks[kg*TS_LD + k0 + q];
                uint32_t b1 = Ks[kg*TS_LD + k0 + q + 4];
                mma_tf32(c[kt], qa[kc][0], qa[kc][1], qa[kc][2], qa[kc][3], b0, b1);
            }
        }

        // chunk max
        float mx0 = -1e30f, mx1 = -1e30f;
#pragma unroll
        for (int kt = 0; kt < 12; ++kt) {
            mx0 = fmaxf(mx0, fmaxf(c[kt].x, c[kt].y));
            mx1 = fmaxf(mx1, fmaxf(c[kt].z, c[kt].w));
        }
        mx0 = fmaxf(mx0, __shfl_xor_sync(0xffffffffu, mx0, 1));
        mx0 = fmaxf(mx0, __shfl_xor_sync(0xffffffffu, mx0, 2));
        mx1 = fmaxf(mx1, __shfl_xor_sync(0xffffffffu, mx1, 1));
        mx1 = fmaxf(mx1, __shfl_xor_sync(0xffffffffu, mx1, 2));

        float mn0 = fmaxf(m0r, mx0), mn1 = fmaxf(m1r, mx1);
        float sc0 = __expf(m0r - mn0), sc1 = __expf(m1r - mn1);
        m0r = mn0; m1r = mn1;

        // exp + chunk sum
        float cs0 = 0.f, cs1 = 0.f;
#pragma unroll
        for (int kt = 0; kt < 12; ++kt) {
            c[kt].x = __expf(c[kt].x - mn0);
            c[kt].y = __expf(c[kt].y - mn0);
            c[kt].z = __expf(c[kt].z - mn1);
            c[kt].w = __expf(c[kt].w - mn1);
            cs0 += c[kt].x + c[kt].y;
            cs1 += c[kt].z + c[kt].w;
        }
        cs0 += __shfl_xor_sync(0xffffffffu, cs0, 1);
        cs0 += __shfl_xor_sync(0xffffffffu, cs0, 2);
        cs1 += __shfl_xor_sync(0xffffffffu, cs1, 1);
        cs1 += __shfl_xor_sync(0xffffffffu, cs1, 2);
        s0r = s0r*sc0 + cs0;
        s1r = s1r*sc1 + cs1;

        // rescale O
#pragma unroll
        for (int nj = 0; nj < 4; ++nj) {
            o[nj].x *= sc0; o[nj].y *= sc0;
            o[nj].z *= sc1; o[nj].w *= sc1;
        }

        // PV accumulate over this chunk's 96 keys
#pragma unroll
        for (int kt = 0; kt < 12; ++kt) {
            float t0 = __shfl_sync(0xffffffffu, c[kt].x, srcA);
            float t1 = __shfl_sync(0xffffffffu, c[kt].y, srcA);
            float t2 = __shfl_sync(0xffffffffu, c[kt].z, srcA);
            float t3 = __shfl_sync(0xffffffffu, c[kt].w, srcA);
            float t4 = __shfl_sync(0xffffffffu, c[kt].x, srcB);
            float t5 = __shfl_sync(0xffffffffu, c[kt].y, srcB);
            float t6 = __shfl_sync(0xffffffffu, c[kt].z, srcB);
            float t7 = __shfl_sync(0xffffffffu, c[kt].w, srcB);
            uint32_t a0 = f2tf((q & 1) ? t1 : t0);
            uint32_t a1 = f2tf((q & 1) ? t3 : t2);
            uint32_t a2 = f2tf((q & 1) ? t5 : t4);
            uint32_t a3 = f2tf((q & 1) ? t7 : t6);
            int col = cbase + kt*8;
            int off = (col >= i*INTV) ? INTV : 0;
            int kg0 = col + q + off;
#pragma unroll
            for (int nj = 0; nj < 4; ++nj) {
                uint32_t b0 = Vs[kg0*TS_LD     + nj*8 + g];
                uint32_t b1 = Vs[(kg0+4)*TS_LD + nj*8 + g];
                mma_tf32(o[nj], a0, a1, a2, a3, b0, b1);
            }
        }
    }

    float inv0 = 1.f / s0r;
    float inv1 = 1.f / s1r;

    // normalize + write (warp-exclusive rows)
#pragma unroll
    for (int nj = 0; nj < 4; ++nj) {
        int cb = h*DH + nj*8 + 2*q;
        float2 v0 = make_float2(o[nj].x * inv0, o[nj].y * inv0);
        float2 v1 = make_float2(o[nj].z * inv1, o[nj].w * inv1);
        *(float2*)&g_att[((size_t)b*N_ + r0g)*C_ + cb] = v0;
        *(float2*)&g_att[((size_t)b*N_ + r1g)*C_ + cb] = v1;
    }
}

// ---------------------------------------------------------------------------
// Launch
// ---------------------------------------------------------------------------
extern "C" void kernel_launch(void* const* d_in, const int* in_sizes, int n_in,
                              void* d_out, int out_size) {
    const float* x      = (const float*)d_in[0];
    const float* q_w    = (const float*)d_in[1];
    const float* kv_w   = (const float*)d_in[2];
    const float* proj_w = (const float*)d_in[3];
    const float* proj_b = (const float*)d_in[4];
    const float* rpb    = (const float*)d_in[5];
    const int*   rel    = (const int*)d_in[6];
    float* out = (float*)d_out;

    const int qkv_smem  = (256*QA_LD + 2*128*QB_LD) * 4;  // 204,800 B
    const int proj_smem = (256*QA_LD + 128*PB_LD) * 4;    // 202,752 B
    const int attn_smem = (2*256*TS_LD) * 4;              // 73,728 B -> 2 CTAs/SM
    cudaFuncSetAttribute(qkv_gemm_tc,  cudaFuncAttributeMaxDynamicSharedMemorySize, qkv_smem);
    cudaFuncSetAttribute(proj_gemm_tc, cudaFuncAttributeMaxDynamicSharedMemorySize, proj_smem);
    cudaFuncSetAttribute(attn_tc,      cudaFuncAttributeMaxDynamicSharedMemorySize, attn_smem);

    bias_kernel<<<(T_*H_*INTV*KN + 255)/256, 256>>>(rpb, rel);
    qkv_gemm_tc<<<(B_*N_)/256, 512, qkv_smem>>>(x, q_w, kv_w);
    attn_tc<<<B_*H_*2, 256, attn_smem>>>();
    proj_gemm_tc<<<(B_*N_)/256, 512, proj_smem>>>(proj_w, proj_b, out);
}

// round 7
// speedup vs baseline: 1.1922x; 1.0268x over previous
#include <cuda_runtime.h>
#include <cstdint>

// Problem constants
#define B_   1024
#define N_   256
#define C_   128
#define H_   4
#define T_   4
#define DH   32
#define INTV 64
#define KN   192   // keys per slice = N - INTV

// Scratch (device globals; no dynamic allocation allowed)
__device__ float g_q[(size_t)B_*H_*N_*DH];       // [b][h][n][d]
__device__ float g_k[(size_t)B_*H_*N_*DH];
__device__ float g_v[(size_t)B_*H_*N_*DH];
__device__ float g_att[(size_t)B_*N_*C_];        // attention output, [b*n][c]
__device__ float g_bias[T_*H_*INTV*KN];          // [i][h][q][kk]

// ---------------------------------------------------------------------------
// helpers
// ---------------------------------------------------------------------------
__device__ __forceinline__ uint32_t f2tf(float f) {
    uint32_t u;
    asm("cvt.rna.tf32.f32 %0, %1;" : "=r"(u) : "f"(f));
    return u;
}

__device__ __forceinline__ void mma_tf32(float4& d,
                                         uint32_t a0, uint32_t a1, uint32_t a2, uint32_t a3,
                                         uint32_t b0, uint32_t b1) {
    asm volatile(
        "mma.sync.aligned.m16n8k8.row.col.f32.tf32.tf32.f32 "
        "{%0,%1,%2,%3}, {%4,%5,%6,%7}, {%8,%9}, {%0,%1,%2,%3};"
        : "+f"(d.x), "+f"(d.y), "+f"(d.z), "+f"(d.w)
        : "r"(a0), "r"(a1), "r"(a2), "r"(a3), "r"(b0), "r"(b1));
}

// ---------------------------------------------------------------------------
// Bias precompute
// ---------------------------------------------------------------------------
__global__ void bias_kernel(const float* __restrict__ rpb,
                            const int* __restrict__ rel) {
    int idx = blockIdx.x * 256 + threadIdx.x;
    if (idx >= T_*H_*INTV*KN) return;
    int kk = idx % KN;
    int q  = (idx / KN) % INTV;
    int h  = (idx / (KN*INTV)) % H_;
    int i  =  idx / (KN*INTV*H_);
    int qg = i*INTV + q;
    int kg = (kk < i*INTV) ? kk : kk + INTV;
    g_bias[idx] = rpb[rel[qg*N_ + kg]*H_ + h];
}

// ---------------------------------------------------------------------------
// QKV GEMM: 256 threads, 128-row M-tile (A resident), 6 N-chunks of 64.
// smem = 128*132 + 128*72 words = 104,448 B -> 2 CTAs/SM. 8 warps 4(m)x2(n),
// warp tile 32x32.
// ---------------------------------------------------------------------------
#define GA_LD 132   // A row stride (mod 32 == 4 -> conflict-free frag loads)
#define GB_LD 72    // B row stride (mod 32 == 8 -> conflict-free frag loads)

__device__ __forceinline__ void store_qkv(int m, int cg, float2 v) {
    int b = m >> 8, n = m & 255;
    if (cg < 128) {
        int h = cg >> 5, d = cg & 31;
        *(float2*)&g_q[(((size_t)b*H_ + h)*N_ + n)*DH + d] = v;
    } else if (cg < 256) {
        int cc = cg - 128; int h = cc >> 5, d = cc & 31;
        *(float2*)&g_k[(((size_t)b*H_ + h)*N_ + n)*DH + d] = v;
    } else {
        int cc = cg - 256; int h = cc >> 5, d = cc & 31;
        *(float2*)&g_v[(((size_t)b*H_ + h)*N_ + n)*DH + d] = v;
    }
}

__global__ __launch_bounds__(256, 2) void qkv_gemm_tc(const float* __restrict__ x,
                                                      const float* __restrict__ q_w,
                                                      const float* __restrict__ kv_w) {
    extern __shared__ uint32_t sm[];
    uint32_t* As = sm;                   // [128][GA_LD]
    uint32_t* Bs = sm + 128*GA_LD;       // [128][GB_LD]

    int tid   = threadIdx.x;
    int mBase = blockIdx.x * 128;

#pragma unroll
    for (int it = 0; it < 16; ++it) {    // A: 128x128
        int idx = tid + it*256;
        int r = idx >> 5, c4 = idx & 31;
        float4 v = *(const float4*)(x + (size_t)(mBase + r)*128 + c4*4);
        uint32_t* p = As + r*GA_LD + c4*4;
        p[0] = f2tf(v.x); p[1] = f2tf(v.y); p[2] = f2tf(v.z); p[3] = f2tf(v.w);
    }

    int warp = tid >> 5, lane = tid & 31;
    int g = lane >> 2, q = lane & 3;
    int wm = (warp & 3) * 32;
    int wn = (warp >> 2) * 32;

#pragma unroll 1
    for (int c = 0; c < 6; ++c) {
        const float* Bp; int bld, bcol;
        if (c < 2) { Bp = q_w;  bld = 128; bcol = c*64; }
        else       { Bp = kv_w; bld = 256; bcol = (c-2)*64; }

        __syncthreads();
#pragma unroll
        for (int it = 0; it < 8; ++it) {  // B chunk: 128x64
            int idx = tid + it*256;
            int r = idx >> 4, c4 = idx & 15;
            float4 v = *(const float4*)(Bp + (size_t)r*bld + bcol + c4*4);
            uint32_t* p = Bs + r*GB_LD + c4*4;
            p[0] = f2tf(v.x); p[1] = f2tf(v.y); p[2] = f2tf(v.z); p[3] = f2tf(v.w);
        }
        __syncthreads();

        float4 acc[2][4];
#pragma unroll
        for (int mi = 0; mi < 2; ++mi)
#pragma unroll
            for (int nj = 0; nj < 4; ++nj) acc[mi][nj] = make_float4(0.f,0.f,0.f,0.f);

#pragma unroll
        for (int k0 = 0; k0 < 128; k0 += 8) {
            uint32_t a[2][4];
#pragma unroll
            for (int mi = 0; mi < 2; ++mi) {
                int r = wm + mi*16 + g;
                a[mi][0] = As[r*GA_LD + k0 + q];
                a[mi][1] = As[(r+8)*GA_LD + k0 + q];
                a[mi][2] = As[r*GA_LD + k0 + q + 4];
                a[mi][3] = As[(r+8)*GA_LD + k0 + q + 4];
            }
#pragma unroll
            for (int nj = 0; nj < 4; ++nj) {
                uint32_t b0 = Bs[(k0+q)*GB_LD   + wn + nj*8 + g];
                uint32_t b1 = Bs[(k0+q+4)*GB_LD + wn + nj*8 + g];
#pragma unroll
                for (int mi = 0; mi < 2; ++mi)
                    mma_tf32(acc[mi][nj], a[mi][0], a[mi][1], a[mi][2], a[mi][3], b0, b1);
            }
        }

#pragma unroll
        for (int mi = 0; mi < 2; ++mi)
#pragma unroll
            for (int nj = 0; nj < 4; ++nj) {
                int r  = mBase + wm + mi*16 + g;
                int cg = c*64 + wn + nj*8 + 2*q;
                store_qkv(r,     cg, make_float2(acc[mi][nj].x, acc[mi][nj].y));
                store_qkv(r + 8, cg, make_float2(acc[mi][nj].z, acc[mi][nj].w));
            }
    }
}

// ---------------------------------------------------------------------------
// Projection GEMM: 256 threads, 128-row M-tile, 2 N-chunks of 64.
// Same 2-CTA/SM budget as qkv. out = g_att @ pw + pb.
// ---------------------------------------------------------------------------
__global__ __launch_bounds__(256, 2) void proj_gemm_tc(const float* __restrict__ pw,
                                                       const float* __restrict__ pb,
                                                       float* __restrict__ out) {
    extern __shared__ uint32_t sm[];
    uint32_t* As = sm;                   // [128][GA_LD]
    uint32_t* Bs = sm + 128*GA_LD;       // [128][GB_LD]

    int tid   = threadIdx.x;
    int mBase = blockIdx.x * 128;

#pragma unroll
    for (int it = 0; it < 16; ++it) {    // A: 128x128
        int idx = tid + it*256;
        int r = idx >> 5, c4 = idx & 31;
        float4 v = *(const float4*)(g_att + (size_t)(mBase + r)*128 + c4*4);
        uint32_t* p = As + r*GA_LD + c4*4;
        p[0] = f2tf(v.x); p[1] = f2tf(v.y); p[2] = f2tf(v.z); p[3] = f2tf(v.w);
    }

    int warp = tid >> 5, lane = tid & 31;
    int g = lane >> 2, q = lane & 3;
    int wm = (warp & 3) * 32;
    int wn = (warp >> 2) * 32;

#pragma unroll 1
    for (int c = 0; c < 2; ++c) {
        __syncthreads();
#pragma unroll
        for (int it = 0; it < 8; ++it) {  // B chunk: 128x64
            int idx = tid + it*256;
            int r = idx >> 4, c4 = idx & 15;
            float4 v = *(const float4*)(pw + (size_t)r*128 + c*64 + c4*4);
            uint32_t* p = Bs + r*GB_LD + c4*4;
            p[0] = f2tf(v.x); p[1] = f2tf(v.y); p[2] = f2tf(v.z); p[3] = f2tf(v.w);
        }
        __syncthreads();

        float4 acc[2][4];
#pragma unroll
        for (int mi = 0; mi < 2; ++mi)
#pragma unroll
            for (int nj = 0; nj < 4; ++nj) acc[mi][nj] = make_float4(0.f,0.f,0.f,0.f);

#pragma unroll
        for (int k0 = 0; k0 < 128; k0 += 8) {
            uint32_t a[2][4];
#pragma unroll
            for (int mi = 0; mi < 2; ++mi) {
                int r = wm + mi*16 + g;
                a[mi][0] = As[r*GA_LD + k0 + q];
                a[mi][1] = As[(r+8)*GA_LD + k0 + q];
                a[mi][2] = As[r*GA_LD + k0 + q + 4];
                a[mi][3] = As[(r+8)*GA_LD + k0 + q + 4];
            }
#pragma unroll
            for (int nj = 0; nj < 4; ++nj) {
                uint32_t b0 = Bs[(k0+q)*GB_LD   + wn + nj*8 + g];
                uint32_t b1 = Bs[(k0+q+4)*GB_LD + wn + nj*8 + g];
#pragma unroll
                for (int mi = 0; mi < 2; ++mi)
                    mma_tf32(acc[mi][nj], a[mi][0], a[mi][1], a[mi][2], a[mi][3], b0, b1);
            }
        }

#pragma unroll
        for (int nj = 0; nj < 4; ++nj) {
            int cg = c*64 + wn + nj*8 + 2*q;
            float2 bias = *(const float2*)(pb + cg);
#pragma unroll
            for (int mi = 0; mi < 2; ++mi) {
                int r = mBase + wm + mi*16 + g;
                float2 v0 = make_float2(acc[mi][nj].x + bias.x, acc[mi][nj].y + bias.y);
                float2 v1 = make_float2(acc[mi][nj].z + bias.x, acc[mi][nj].w + bias.y);
                *(float2*)&out[(size_t)r*C_ + cg]     = v0;
                *(float2*)&out[(size_t)(r+8)*C_ + cg] = v1;
            }
        }
    }
}

// ---------------------------------------------------------------------------
// Attention: block per (b, h, half) -> 8192 blocks, 256 threads (8 warps),
// 2 CTAs/SM. (identical to verified R6 version)
// ---------------------------------------------------------------------------
#define TS_LD 36

__global__ __launch_bounds__(256, 2) void attn_tc() {
    extern __shared__ uint32_t sm[];
    uint32_t* Ks = sm;                   // [256][TS_LD]
    uint32_t* Vs = sm + 256*TS_LD;

    int tid = threadIdx.x;
    int bid = blockIdx.x;
    int hb = bid & 1;
    int h  = (bid >> 1) & 3;
    int b  = bid >> 3;
    size_t base = ((size_t)b*H_ + h) * N_ * DH;

    const float scale = 0.17677669529663687f;  // 32^-0.5

#pragma unroll
    for (int it = 0; it < 8; ++it) {     // K,V: 256x32 each
        int idx = tid + it*256;
        int r = idx >> 3, c4 = idx & 7;
        float4 kv = *(const float4*)(g_k + base + (size_t)r*DH + c4*4);
        float4 vv = *(const float4*)(g_v + base + (size_t)r*DH + c4*4);
        uint32_t* pk = Ks + r*TS_LD + c4*4;
        pk[0] = f2tf(kv.x); pk[1] = f2tf(kv.y); pk[2] = f2tf(kv.z); pk[3] = f2tf(kv.w);
        uint32_t* pv = Vs + r*TS_LD + c4*4;
        pv[0] = f2tf(vv.x); pv[1] = f2tf(vv.y); pv[2] = f2tf(vv.z); pv[3] = f2tf(vv.w);
    }

    int warp = tid >> 5, lane = tid & 31;
    int g = lane >> 2, q = lane & 3;
    int rloc = warp * 16;                // 0..112 within half
    int i = hb*2 + (warp >> 2);          // slice
    int r0g = hb*128 + rloc + g;         // global query rows
    int r1g = r0g + 8;

    // Q A-frags direct from gmem (overlaps K/V staging latency)
    uint32_t qa[4][4];
    {
        const float* qp0 = g_q + base + (size_t)r0g*DH;
        const float* qp1 = g_q + base + (size_t)r1g*DH;
#pragma unroll
        for (int kc = 0; kc < 4; ++kc) {
            qa[kc][0] = f2tf(qp0[kc*8 + q]     * scale);
            qa[kc][1] = f2tf(qp1[kc*8 + q]     * scale);
            qa[kc][2] = f2tf(qp0[kc*8 + q + 4] * scale);
            qa[kc][3] = f2tf(qp1[kc*8 + q + 4] * scale);
        }
    }
    __syncthreads();

    const float* bb = g_bias + ((size_t)((i*H_ + h)*INTV + (rloc & 63)))*KN;
    int srcA = (lane & ~3) | (q >> 1);
    int srcB = srcA + 2;

    float m0r = -1e30f, m1r = -1e30f;
    float s0r = 0.f, s1r = 0.f;
    float4 o[4];
#pragma unroll
    for (int nj = 0; nj < 4; ++nj) o[nj] = make_float4(0.f,0.f,0.f,0.f);

#pragma unroll
    for (int ch = 0; ch < 2; ++ch) {
        int cbase = ch * 96;

        // S frags (16 x 96), bias-initialized
        float4 c[12];
#pragma unroll
        for (int kt = 0; kt < 12; ++kt) {
            int col = cbase + kt*8 + 2*q;
            float2 b0 = *(const float2*)(bb + (size_t)(g)*KN + col);
            float2 b1 = *(const float2*)(bb + (size_t)(g+8)*KN + col);
            c[kt] = make_float4(b0.x, b0.y, b1.x, b1.y);
        }

        // S = scale*Q K^T + bias (keys mapped around excluded slice)
#pragma unroll
        for (int kc = 0; kc < 4; ++kc) {
            int k0 = kc*8;
#pragma unroll
            for (int kt = 0; kt < 12; ++kt) {
                int col = cbase + kt*8;
                int off = (col >= i*INTV) ? INTV : 0;
                int kg = col + g + off;
                uint32_t b0 = Ks[kg*TS_LD + k0 + q];
                uint32_t b1 = Ks[kg*TS_LD + k0 + q + 4];
                mma_tf32(c[kt], qa[kc][0], qa[kc][1], qa[kc][2], qa[kc][3], b0, b1);
            }
        }

        // chunk max
        float mx0 = -1e30f, mx1 = -1e30f;
#pragma unroll
        for (int kt = 0; kt < 12; ++kt) {
            mx0 = fmaxf(mx0, fmaxf(c[kt].x, c[kt].y));
            mx1 = fmaxf(mx1, fmaxf(c[kt].z, c[kt].w));
        }
        mx0 = fmaxf(mx0, __shfl_xor_sync(0xffffffffu, mx0, 1));
        mx0 = fmaxf(mx0, __shfl_xor_sync(0xffffffffu, mx0, 2));
        mx1 = fmaxf(mx1, __shfl_xor_sync(0xffffffffu, mx1, 1));
        mx1 = fmaxf(mx1, __shfl_xor_sync(0xffffffffu, mx1, 2));

        float mn0 = fmaxf(m0r, mx0), mn1 = fmaxf(m1r, mx1);
        float sc0 = __expf(m0r - mn0), sc1 = __expf(m1r - mn1);
        m0r = mn0; m1r = mn1;

        // exp + chunk sum
        float cs0 = 0.f, cs1 = 0.f;
#pragma unroll
        for (int kt = 0; kt < 12; ++kt) {
            c[kt].x = __expf(c[kt].x - mn0);
            c[kt].y = __expf(c[kt].y - mn0);
            c[kt].z = __expf(c[kt].z - mn1);
            c[kt].w = __expf(c[kt].w - mn1);
            cs0 += c[kt].x + c[kt].y;
            cs1 += c[kt].z + c[kt].w;
        }
        cs0 += __shfl_xor_sync(0xffffffffu, cs0, 1);
        cs0 += __shfl_xor_sync(0xffffffffu, cs0, 2);
        cs1 += __shfl_xor_sync(0xffffffffu, cs1, 1);
        cs1 += __shfl_xor_sync(0xffffffffu, cs1, 2);
        s0r = s0r*sc0 + cs0;
        s1r = s1r*sc1 + cs1;

        // rescale O
#pragma unroll
        for (int nj = 0; nj < 4; ++nj) {
            o[nj].x *= sc0; o[nj].y *= sc0;
            o[nj].z *= sc1; o[nj].w *= sc1;
        }

        // PV accumulate over this chunk's 96 keys
#pragma unroll
        for (int kt = 0; kt < 12; ++kt) {
            float t0 = __shfl_sync(0xffffffffu, c[kt].x, srcA);
            float t1 = __shfl_sync(0xffffffffu, c[kt].y, srcA);
            float t2 = __shfl_sync(0xffffffffu, c[kt].z, srcA);
            float t3 = __shfl_sync(0xffffffffu, c[kt].w, srcA);
            float t4 = __shfl_sync(0xffffffffu, c[kt].x, srcB);
            float t5 = __shfl_sync(0xffffffffu, c[kt].y, srcB);
            float t6 = __shfl_sync(0xffffffffu, c[kt].z, srcB);
            float t7 = __shfl_sync(0xffffffffu, c[kt].w, srcB);
            uint32_t a0 = f2tf((q & 1) ? t1 : t0);
            uint32_t a1 = f2tf((q & 1) ? t3 : t2);
            uint32_t a2 = f2tf((q & 1) ? t5 : t4);
            uint32_t a3 = f2tf((q & 1) ? t7 : t6);
            int col = cbase + kt*8;
            int off = (col >= i*INTV) ? INTV : 0;
            int kg0 = col + q + off;
#pragma unroll
            for (int nj = 0; nj < 4; ++nj) {
                uint32_t b0 = Vs[kg0*TS_LD     + nj*8 + g];
                uint32_t b1 = Vs[(kg0+4)*TS_LD + nj*8 + g];
                mma_tf32(o[nj], a0, a1, a2, a3, b0, b1);
            }
        }
    }

    float inv0 = 1.f / s0r;
    float inv1 = 1.f / s1r;

    // normalize + write (warp-exclusive rows)
#pragma unroll
    for (int nj = 0; nj < 4; ++nj) {
        int cb = h*DH + nj*8 + 2*q;
        float2 v0 = make_float2(o[nj].x * inv0, o[nj].y * inv0);
        float2 v1 = make_float2(o[nj].z * inv1, o[nj].w * inv1);
        *(float2*)&g_att[((size_t)b*N_ + r0g)*C_ + cb] = v0;
        *(float2*)&g_att[((size_t)b*N_ + r1g)*C_ + cb] = v1;
    }
}

// ---------------------------------------------------------------------------
// Launch
// ---------------------------------------------------------------------------
extern "C" void kernel_launch(void* const* d_in, const int* in_sizes, int n_in,
                              void* d_out, int out_size) {
    const float* x      = (const float*)d_in[0];
    const float* q_w    = (const float*)d_in[1];
    const float* kv_w   = (const float*)d_in[2];
    const float* proj_w = (const float*)d_in[3];
    const float* proj_b = (const float*)d_in[4];
    const float* rpb    = (const float*)d_in[5];
    const int*   rel    = (const int*)d_in[6];
    float* out = (float*)d_out;

    const int gemm_smem = (128*GA_LD + 128*GB_LD) * 4;   // 104,448 B -> 2 CTAs/SM
    const int attn_smem = (2*256*TS_LD) * 4;             // 73,728 B  -> 2 CTAs/SM
    cudaFuncSetAttribute(qkv_gemm_tc,  cudaFuncAttributeMaxDynamicSharedMemorySize, gemm_smem);
    cudaFuncSetAttribute(proj_gemm_tc, cudaFuncAttributeMaxDynamicSharedMemorySize, gemm_smem);
    cudaFuncSetAttribute(attn_tc,      cudaFuncAttributeMaxDynamicSharedMemorySize, attn_smem);

    bias_kernel<<<(T_*H_*INTV*KN + 255)/256, 256>>>(rpb, rel);
    qkv_gemm_tc<<<(B_*N_)/128, 256, gemm_smem>>>(x, q_w, kv_w);
    attn_tc<<<B_*H_*2, 256, attn_smem>>>();
    proj_gemm_tc<<<(B_*N_)/128, 256, gemm_smem>>>(proj_w, proj_b, out);
}